// round 1
// baseline (speedup 1.0000x reference)
#include <cuda_runtime.h>
#include <cuda_bf16.h>
#include <cstdint>

#define NNODES 50000
#define HID    128
#define MAXD   16
#define NGRAPH 50
#define NCLS   10
#define GRUH   32

// ---------------- scratch (static device globals: no allocs allowed) --------
__device__ float g_P  [(size_t)NNODES * 512];   // feature@Wih^T + bih + bhh
__device__ float g_hT [(size_t)NNODES * HID];   // LSTM final hidden
__device__ float g_h1 [(size_t)NNODES * HID];   // after SAGE relu
__device__ float g_agg[(size_t)NNODES * HID];   // graphconv aggregate (normed)
__device__ float g_h2 [(size_t)NNODES * HID];   // after graphconv relu
__device__ float g_o32[(size_t)NNODES * GRUH];  // GRU output
__device__ uint2 g_Whh4 [HID * HID];            // [k][m] -> 4 bf16 (i,f,g,o)
__device__ float g_WihT [HID * 512];            // [k][j]
__device__ float g_biasP[512];                  // bih + bhh
__device__ float4 g_Wt3 [HID * GRUH];           // [k][l] -> (Wr,Wz,Wn,0)

// ---------------- helpers ----------------
__device__ __forceinline__ float sigf(float x) {
    x = fminf(fmaxf(x, -30.f), 30.f);
    return __fdividef(1.f, 1.f + __expf(-x));
}
__device__ __forceinline__ float tanh_(float x) {
    x = fminf(fmaxf(x, -15.f), 15.f);
    float e = __expf(-2.f * x);
    return __fdividef(1.f - e, 1.f + e);
}
__device__ __forceinline__ unsigned short bf16u(float x) {
    __nv_bfloat16 b = __float2bfloat16(x);
    return *reinterpret_cast<unsigned short*>(&b);
}

// ---------------- prep: transposes / packing ----------------
__global__ void prep_kernel(const float* __restrict__ Wih,
                            const float* __restrict__ Whh,
                            const float* __restrict__ bih,
                            const float* __restrict__ bhh,
                            const float* __restrict__ Wgru) {
    int idx = blockIdx.x * blockDim.x + threadIdx.x;
    if (idx < HID * 512) {               // WihT[k*512 + j] = Wih[j*128 + k]
        int k = idx & 127, j = idx >> 7;
        g_WihT[k * 512 + j] = Wih[j * HID + k];
    }
    if (idx < HID * HID) {               // pack Whh gates bf16
        int k = idx >> 7, m = idx & 127;
        unsigned wi = bf16u(Whh[(0 * HID + m) * HID + k]);
        unsigned wf = bf16u(Whh[(1 * HID + m) * HID + k]);
        unsigned wg = bf16u(Whh[(2 * HID + m) * HID + k]);
        unsigned wo = bf16u(Whh[(3 * HID + m) * HID + k]);
        g_Whh4[idx] = make_uint2(wi | (wf << 16), wg | (wo << 16));
    }
    if (idx < 512) g_biasP[idx] = bih[idx] + bhh[idx];
    if (idx < HID * GRUH) {              // [k][l] packed r,z,n columns
        int k = idx >> 5, l = idx & 31;
        g_Wt3[idx] = make_float4(Wgru[(0 * GRUH + l) * HID + k],
                                 Wgru[(1 * GRUH + l) * HID + k],
                                 Wgru[(2 * GRUH + l) * HID + k], 0.f);
    }
}

// ---------------- generic K=128 GEMM:  C = act(A@W [+ A2@W2] + bias) -------
// W is [128, N] row-major. BM=BN=64, BK=32, 256 threads, 4x4 per thread.
__global__ void gemm128(const float* __restrict__ A,  const float* __restrict__ W,
                        const float* __restrict__ A2, const float* __restrict__ W2,
                        const float* __restrict__ bias, float* __restrict__ C,
                        int M, int N, int relu) {
    __shared__ float Asm[32][68];
    __shared__ float Wsm[32][64];
    int tid = threadIdx.x;
    int tx = tid & 15, ty = tid >> 4;
    int r0 = blockIdx.x * 64, c0 = blockIdx.y * 64;

    float acc[4][4];
#pragma unroll
    for (int i = 0; i < 4; i++)
#pragma unroll
        for (int j = 0; j < 4; j++) acc[i][j] = 0.f;

    int npass = (A2 != nullptr) ? 2 : 1;
    for (int p = 0; p < npass; ++p) {
        const float* Ap = p ? A2 : A;
        const float* Wp = p ? W2 : W;
        for (int kk = 0; kk < 128; kk += 32) {
            __syncthreads();
            {   // A chunk: 64 rows x 32 k, stored transposed
                int k = tid & 31, r = tid >> 5;
#pragma unroll
                for (int pp = 0; pp < 8; ++pp) {
                    int row = r0 + r + pp * 8;
                    row = min(row, M - 1);
                    Asm[k][r + pp * 8] = Ap[(size_t)row * 128 + kk + k];
                }
            }
            {   // W chunk: 32 k x 64 cols
                int c = tid & 63, kq = tid >> 6;
#pragma unroll
                for (int pp = 0; pp < 8; ++pp)
                    Wsm[kq + pp * 4][c] = Wp[(size_t)(kk + kq + pp * 4) * N + c0 + c];
            }
            __syncthreads();
#pragma unroll
            for (int k = 0; k < 32; ++k) {
                float4 a4 = *(const float4*)&Asm[k][ty * 4];
                float4 w4 = *(const float4*)&Wsm[k][tx * 4];
                float ar[4] = {a4.x, a4.y, a4.z, a4.w};
                float wc[4] = {w4.x, w4.y, w4.z, w4.w};
#pragma unroll
                for (int i = 0; i < 4; i++)
#pragma unroll
                    for (int j = 0; j < 4; j++)
                        acc[i][j] = fmaf(ar[i], wc[j], acc[i][j]);
            }
        }
    }
#pragma unroll
    for (int i = 0; i < 4; i++) {
        int row = r0 + ty * 4 + i;
        if (row < M) {
#pragma unroll
            for (int j = 0; j < 4; j++) {
                int col = c0 + tx * 4 + j;
                float v = acc[i][j] + (bias ? bias[col] : 0.f);
                if (relu) v = fmaxf(v, 0.f);
                C[(size_t)row * N + col] = v;
            }
        }
    }
}

// ---------------- fused LSTM recurrence (persistent) ----------------
// 512 threads = 4 groups of 128; each group owns one node at a time.
// Whh (bf16-packed) cached once per block in shared memory.
__global__ void lstm_kernel(const int* __restrict__ nbr, const int* __restrict__ deg) {
    extern __shared__ char smem[];
    uint2* whh = (uint2*)smem;                   // 16384 * 8B = 128 KB
    float* hsm = (float*)(smem + 131072);        // 4 * 128 floats

    int tid = threadIdx.x;
    for (int i = tid; i < HID * HID; i += blockDim.x) whh[i] = g_Whh4[i];
    __syncthreads();

    int grp = tid >> 7;          // 0..3
    int m   = tid & 127;
    float* hg = hsm + grp * 128;
    int bar = grp + 1;           // named barrier id (avoid 0)

    for (int node = blockIdx.x * 4 + grp; node < NNODES; node += gridDim.x * 4) {
        int d = deg[node];
        const int* nb = nbr + node * MAXD;
        float h = 0.f, c = 0.f;
        for (int t = 0; t < d; ++t) {
            int u = nb[t];
            const float* pr = g_P + (size_t)u * 512;
            // issue gathers early; consumed after the k-loop
            float pi = pr[m], pf = pr[m + 128], pg = pr[m + 256], po = pr[m + 384];
            hg[m] = h;
            asm volatile("bar.sync %0, %1;" :: "r"(bar), "r"(128) : "memory");
            float ai = 0.f, af = 0.f, ag = 0.f, ao = 0.f;
#pragma unroll 8
            for (int k0 = 0; k0 < 128; k0 += 4) {
                float4 h4 = *(const float4*)(hg + k0);
                float hks[4] = {h4.x, h4.y, h4.z, h4.w};
#pragma unroll
                for (int q = 0; q < 4; ++q) {
                    float hk = hks[q];
                    uint2 w = whh[(k0 + q) * 128 + m];
                    ai = fmaf(hk, __uint_as_float(w.x << 16),         ai);
                    af = fmaf(hk, __uint_as_float(w.x & 0xFFFF0000u), af);
                    ag = fmaf(hk, __uint_as_float(w.y << 16),         ag);
                    ao = fmaf(hk, __uint_as_float(w.y & 0xFFFF0000u), ao);
                }
            }
            asm volatile("bar.sync %0, %1;" :: "r"(bar), "r"(128) : "memory");
            ai += pi; af += pf; ag += pg; ao += po;
            float cn = sigf(af) * c + sigf(ai) * tanh_(ag);
            c = cn;
            h = sigf(ao) * tanh_(cn);
        }
        g_hT[(size_t)node * 128 + m] = h;
    }
}

// ---------------- GraphConv aggregate: warp per node ----------------
__global__ void agg_kernel(const int* __restrict__ nbr, const int* __restrict__ deg) {
    int wid  = (blockIdx.x * blockDim.x + threadIdx.x) >> 5;
    int lane = threadIdx.x & 31;
    if (wid >= NNODES) return;
    int d = deg[wid];
    const int* nb = nbr + wid * MAXD;
    float4 acc = {0.f, 0.f, 0.f, 0.f};
    for (int t = 0; t < d; ++t) {
        int u = nb[t];
        float nu = rsqrtf((float)max(deg[u], 1));
        float4 v = *(const float4*)(g_h1 + (size_t)u * 128 + lane * 4);
        acc.x = fmaf(v.x, nu, acc.x); acc.y = fmaf(v.y, nu, acc.y);
        acc.z = fmaf(v.z, nu, acc.z); acc.w = fmaf(v.w, nu, acc.w);
    }
    float nn = rsqrtf((float)max(d, 1));
    float4 o = {acc.x * nn, acc.y * nn, acc.z * nn, acc.w * nn};
    *(float4*)(g_agg + (size_t)wid * 128 + lane * 4) = o;
}

// ---------------- GRU (seq_len=1, h0=0): warp per node ----------------
__global__ void gru_kernel(const float* __restrict__ bih, const float* __restrict__ bhh) {
    extern __shared__ char sm[];
    float4* Wt   = (float4*)sm;                 // 4096 float4 = 64 KB
    float*  hrow = (float*)(sm + 65536);        // 8 * 128
    int tid = threadIdx.x;
    for (int i = tid; i < HID * GRUH; i += blockDim.x) Wt[i] = g_Wt3[i];
    __syncthreads();

    int w = tid >> 5, lane = tid & 31;
    float br = bih[lane],      bz = bih[32 + lane],  bn = bih[64 + lane];
    float cr = bhh[lane],      cz = bhh[32 + lane],  cnb = bhh[64 + lane];
    float* hr = hrow + w * 128;
    int nwarp = gridDim.x * 8;
    for (int node = blockIdx.x * 8 + w; node < NNODES; node += nwarp) {
        const float* h2 = g_h2 + (size_t)node * 128;
        *(float4*)(hr + lane * 4) = *(const float4*)(h2 + lane * 4);
        __syncwarp();
        float ar = 0.f, az = 0.f, an = 0.f;
#pragma unroll 8
        for (int k = 0; k < 128; ++k) {
            float hk = hr[k];
            float4 wv = Wt[k * 32 + lane];
            ar = fmaf(hk, wv.x, ar);
            az = fmaf(hk, wv.y, az);
            an = fmaf(hk, wv.z, an);
        }
        __syncwarp();
        float r   = sigf(ar + br + cr);
        float z   = sigf(az + bz + cz);
        float nst = tanh_(an + bn + r * cnb);
        g_o32[(size_t)node * 32 + lane] = (1.f - z) * nst;
    }
}

// ---------------- deterministic mean-pool + classifier ----------------
__global__ void pool_kernel(const int* __restrict__ gid,
                            const float* __restrict__ Wc,
                            const float* __restrict__ bc,
                            float* __restrict__ out) {
    __shared__ float s[8][32];
    __shared__ int   scnt[8];
    __shared__ float hg[32];
    int g = blockIdx.x;
    int tid = threadIdx.x, lane = tid & 31, slot = tid >> 5;
    float acc = 0.f;
    int cnt = 0;
    for (int i = slot; i < NNODES; i += 8) {
        if (gid[i] == g) {
            acc += g_o32[(size_t)i * 32 + lane];
            cnt++;
        }
    }
    s[slot][lane] = acc;
    if (lane == 0) scnt[slot] = cnt;
    __syncthreads();
    if (tid < 32) {
        float sum = 0.f; int tot = 0;
#pragma unroll
        for (int j = 0; j < 8; ++j) { sum += s[j][tid]; tot += scnt[j]; }
        hg[tid] = sum / (float)tot;
    }
    __syncthreads();
    if (tid < NCLS) {
        float o = bc[tid];
#pragma unroll
        for (int k = 0; k < 32; ++k) o = fmaf(hg[k], Wc[k * NCLS + tid], o);
        out[g * NCLS + tid] = o;
    }
}

// ---------------- launch ----------------
extern "C" void kernel_launch(void* const* d_in, const int* in_sizes, int n_in,
                              void* d_out, int out_size) {
    const float* feature = (const float*)d_in[0];
    const int*   nbr     = (const int*)  d_in[1];
    const int*   deg     = (const int*)  d_in[2];
    const int*   gid     = (const int*)  d_in[3];
    const float* lWih    = (const float*)d_in[4];
    const float* lWhh    = (const float*)d_in[5];
    const float* lbih    = (const float*)d_in[6];
    const float* lbhh    = (const float*)d_in[7];
    const float* Wself   = (const float*)d_in[8];
    const float* Wneigh  = (const float*)d_in[9];
    const float* bsage   = (const float*)d_in[10];
    const float* Wgc     = (const float*)d_in[11];
    const float* bgc     = (const float*)d_in[12];
    const float* Wgru    = (const float*)d_in[13];
    const float* bihg    = (const float*)d_in[14];
    const float* bhhg    = (const float*)d_in[15];
    const float* Wcls    = (const float*)d_in[16];
    const float* bcls    = (const float*)d_in[17];
    float* out = (float*)d_out;

    cudaFuncSetAttribute(lstm_kernel, cudaFuncAttributeMaxDynamicSharedMemorySize, 133120 + 256);
    cudaFuncSetAttribute(gru_kernel,  cudaFuncAttributeMaxDynamicSharedMemorySize, 69632 + 256);

    float *pP, *phT, *ph1, *pagg, *ph2, *pWihT, *pbiasP;
    cudaGetSymbolAddress((void**)&pP,     g_P);
    cudaGetSymbolAddress((void**)&phT,    g_hT);
    cudaGetSymbolAddress((void**)&ph1,    g_h1);
    cudaGetSymbolAddress((void**)&pagg,   g_agg);
    cudaGetSymbolAddress((void**)&ph2,    g_h2);
    cudaGetSymbolAddress((void**)&pWihT,  g_WihT);
    cudaGetSymbolAddress((void**)&pbiasP, g_biasP);

    prep_kernel<<<256, 256>>>(lWih, lWhh, lbih, lbhh, Wgru);

    // P = feature @ Wih^T + (bih + bhh)      [N, 512]
    {
        dim3 grid((NNODES + 63) / 64, 512 / 64);
        gemm128<<<grid, 256>>>(feature, pWihT, nullptr, nullptr, pbiasP, pP, NNODES, 512, 0);
    }
    // LSTM recurrence (persistent, 1 block/SM)
    lstm_kernel<<<152, 512, 133120 + 256>>>(nbr, deg);
    // h1 = relu(feature@W_self + hT@W_neigh + b_sage)
    {
        dim3 grid((NNODES + 63) / 64, 128 / 64);
        gemm128<<<grid, 256>>>(feature, Wself, phT, Wneigh, bsage, ph1, NNODES, 128, 1);
    }
    // GraphConv aggregate
    agg_kernel<<<(NNODES * 32 + 255) / 256, 256>>>(nbr, deg);
    // h2 = relu(agg @ W_gc + b_gc)
    {
        dim3 grid((NNODES + 63) / 64, 128 / 64);
        gemm128<<<grid, 256>>>(pagg, Wgc, nullptr, nullptr, bgc, ph2, NNODES, 128, 1);
    }
    // GRU step
    gru_kernel<<<304, 256, 69632 + 256>>>(bihg, bhhg);
    // mean pool + classifier
    pool_kernel<<<NGRAPH, 256>>>(gid, Wcls, bcls, out);
}

// round 2
// speedup vs baseline: 1.9172x; 1.9172x over previous
#include <cuda_runtime.h>
#include <cuda_bf16.h>
#include <cstdint>

#define NNODES 50000
#define HID    128
#define MAXD   16
#define NGRAPH 50
#define NCLS   10
#define GRUH   32
#define MAXB   3400

// ---------------- scratch ----------------
__device__ __nv_bfloat16 g_Pb [(size_t)NNODES * 512]; // feature@WihT, bf16, phys-permuted cols
__device__ float g_hT [(size_t)NNODES * HID];
__device__ float g_h1 [(size_t)NNODES * HID];
__device__ float g_agg[(size_t)NNODES * HID];
__device__ float g_h2 [(size_t)NNODES * HID];
__device__ float g_o32[(size_t)NNODES * GRUH];
__device__ float g_WihTp[HID * 512];         // [k][p] permuted
__device__ uint2 g_Wfrag[512 * 32];          // Whh fragments: tile(kt*64+ntg) x lane
__device__ float4 g_biasF[HID];              // (bi,bf,bg,bo) per hidden j
__device__ float4 g_Wt3 [HID * GRUH];        // GRU
// degree bucketing
__device__ int g_order[NNODES];
__device__ int g_bincnt[16];
__device__ int g_binoff[16];
__device__ int g_batch_start[MAXB];
__device__ int g_batch_info[MAXB];           // (deg<<8)|cnt
__device__ int g_nbatch;

// ---------------- helpers ----------------
__device__ __forceinline__ float sigf(float x) {
    x = fminf(fmaxf(x, -30.f), 30.f);
    return __fdividef(1.f, 1.f + __expf(-x));
}
__device__ __forceinline__ float tanh_(float x) {
    x = fminf(fmaxf(x, -15.f), 15.f);
    float e = __expf(-2.f * x);
    return __fdividef(1.f - e, 1.f + e);
}
__device__ __forceinline__ unsigned bf16u(float x) {
    __nv_bfloat16 b = __float2bfloat16(x);
    return (unsigned)*reinterpret_cast<unsigned short*>(&b);
}
__device__ __forceinline__ float blo(unsigned v) { return __uint_as_float(v << 16); }
__device__ __forceinline__ float bhi(unsigned v) { return __uint_as_float(v & 0xFFFF0000u); }

// phys col p -> logical LSTM row (gamma*128+j); gate layout per 16-col block:
// cols 0..7 = (i,f) x4 j's interleaved, cols 8..15 = (g,o) x4 j's
__host__ __device__ __forceinline__ int phys2row(int p) {
    int pb = p >> 4, rem = p & 15;
    int gamma, aa;
    if (rem < 8) { aa = rem >> 1; gamma = (rem & 1) ? 1 : 0; }
    else         { aa = (rem - 8) >> 1; gamma = (rem & 1) ? 3 : 2; }
    return gamma * HID + pb * 4 + aa;
}

__device__ __forceinline__ void mma16816(float* d, const unsigned* a, unsigned b0, unsigned b1) {
    asm volatile(
        "mma.sync.aligned.m16n8k16.row.col.f32.bf16.bf16.f32 "
        "{%0,%1,%2,%3}, {%4,%5,%6,%7}, {%8,%9}, {%0,%1,%2,%3};"
        : "+f"(d[0]), "+f"(d[1]), "+f"(d[2]), "+f"(d[3])
        : "r"(a[0]), "r"(a[1]), "r"(a[2]), "r"(a[3]), "r"(b0), "r"(b1));
}

// ---------------- prep: packing / transposes ----------------
__global__ void prep_kernel(const float* __restrict__ Wih,
                            const float* __restrict__ Whh,
                            const float* __restrict__ bih,
                            const float* __restrict__ bhh,
                            const float* __restrict__ Wgru) {
    int idx = blockIdx.x * blockDim.x + threadIdx.x;
    if (idx < HID * 512) {                   // WihTp[k*512+p]
        int k = idx >> 9, p = idx & 511;
        g_WihTp[idx] = Wih[phys2row(p) * HID + k];
    }
    if (idx < 512 * 32) {                    // Whh fragments
        int t_id = idx >> 5, lane = idx & 31;
        int kt = t_id >> 6, ntg = t_id & 63;
        int p = ntg * 8 + (lane >> 2);
        int wrow = phys2row(p);
        int k0 = kt * 16 + (lane & 3) * 2;
        const float* wr = Whh + (size_t)wrow * HID;
        uint2 v;
        v.x = bf16u(wr[k0])     | (bf16u(wr[k0 + 1]) << 16);
        v.y = bf16u(wr[k0 + 8]) | (bf16u(wr[k0 + 9]) << 16);
        g_Wfrag[idx] = v;
    }
    if (idx < HID) {
        g_biasF[idx] = make_float4(bih[idx] + bhh[idx],
                                   bih[HID + idx] + bhh[HID + idx],
                                   bih[2 * HID + idx] + bhh[2 * HID + idx],
                                   bih[3 * HID + idx] + bhh[3 * HID + idx]);
    }
    if (idx < HID * GRUH) {
        int k = idx >> 5, l = idx & 31;
        g_Wt3[idx] = make_float4(Wgru[(0 * GRUH + l) * HID + k],
                                 Wgru[(1 * GRUH + l) * HID + k],
                                 Wgru[(2 * GRUH + l) * HID + k], 0.f);
    }
}

// ---------------- degree bucketing ----------------
__global__ void k_zero() {
    if (threadIdx.x < 16) g_bincnt[threadIdx.x] = 0;
}
__global__ void k_hist(const int* __restrict__ deg) {
    __shared__ int h[16];
    if (threadIdx.x < 16) h[threadIdx.x] = 0;
    __syncthreads();
    for (int i = blockIdx.x * blockDim.x + threadIdx.x; i < NNODES; i += gridDim.x * blockDim.x)
        atomicAdd(&h[deg[i] - 1], 1);
    __syncthreads();
    if (threadIdx.x < 16) atomicAdd(&g_bincnt[threadIdx.x], h[threadIdx.x]);
}
__global__ void k_batches() {
    __shared__ int bstart[16], boff[16];
    if (threadIdx.x == 0) {
        int off = 0, bo = 0;
        for (int d = 0; d < 16; ++d) {
            bstart[d] = off; g_binoff[d] = off; boff[d] = bo;
            off += g_bincnt[d];
            bo += (g_bincnt[d] + 15) >> 4;
        }
        g_nbatch = bo;
    }
    __syncthreads();
    int d = threadIdx.x;
    if (d < 16) {
        int cnt = g_bincnt[d];
        int bi = boff[d];
        for (int j = 0; j < cnt; j += 16, ++bi) {
            g_batch_start[bi] = bstart[d] + j;
            g_batch_info[bi]  = ((d + 1) << 8) | min(16, cnt - j);
        }
    }
}
__global__ void k_scatter(const int* __restrict__ deg) {
    __shared__ int scnt[16], sbase[16], scur[16];
    int t = threadIdx.x;
    if (t < 16) { scnt[t] = 0; scur[t] = 0; }
    __syncthreads();
    int i = blockIdx.x * 512 + t;
    int d = -1;
    if (i < NNODES) { d = deg[i] - 1; atomicAdd(&scnt[d], 1); }
    __syncthreads();
    if (t < 16 && scnt[t] > 0) sbase[t] = atomicAdd(&g_binoff[t], scnt[t]);
    __syncthreads();
    if (i < NNODES) {
        int pos = sbase[d] + atomicAdd(&scur[d], 1);
        g_order[pos] = i;
    }
}

// ---------------- generic K=128 GEMM ----------------
// W is [128, N] row-major. outmode: 0=f32, 1=f32+relu, 2=bf16
__global__ void gemm128(const float* __restrict__ A,  const float* __restrict__ W,
                        const float* __restrict__ A2, const float* __restrict__ W2,
                        const float* __restrict__ bias, void* __restrict__ C,
                        int M, int N, int outmode) {
    __shared__ float Asm[32][68];
    __shared__ float Wsm[32][64];
    int tid = threadIdx.x;
    int tx = tid & 15, ty = tid >> 4;
    int r0 = blockIdx.x * 64, c0 = blockIdx.y * 64;

    float acc[4][4];
#pragma unroll
    for (int i = 0; i < 4; i++)
#pragma unroll
        for (int j = 0; j < 4; j++) acc[i][j] = 0.f;

    int npass = (A2 != nullptr) ? 2 : 1;
    for (int p = 0; p < npass; ++p) {
        const float* Ap = p ? A2 : A;
        const float* Wp = p ? W2 : W;
        for (int kk = 0; kk < 128; kk += 32) {
            __syncthreads();
            {
                int k = tid & 31, r = tid >> 5;
#pragma unroll
                for (int pp = 0; pp < 8; ++pp) {
                    int row = r0 + r + pp * 8;
                    row = min(row, M - 1);
                    Asm[k][r + pp * 8] = Ap[(size_t)row * 128 + kk + k];
                }
            }
            {
                int c = tid & 63, kq = tid >> 6;
#pragma unroll
                for (int pp = 0; pp < 8; ++pp)
                    Wsm[kq + pp * 4][c] = Wp[(size_t)(kk + kq + pp * 4) * N + c0 + c];
            }
            __syncthreads();
#pragma unroll
            for (int k = 0; k < 32; ++k) {
                float4 a4 = *(const float4*)&Asm[k][ty * 4];
                float4 w4 = *(const float4*)&Wsm[k][tx * 4];
                float ar[4] = {a4.x, a4.y, a4.z, a4.w};
                float wc[4] = {w4.x, w4.y, w4.z, w4.w};
#pragma unroll
                for (int i = 0; i < 4; i++)
#pragma unroll
                    for (int j = 0; j < 4; j++)
                        acc[i][j] = fmaf(ar[i], wc[j], acc[i][j]);
            }
        }
    }
#pragma unroll
    for (int i = 0; i < 4; i++) {
        int row = r0 + ty * 4 + i;
        if (row < M) {
#pragma unroll
            for (int j = 0; j < 4; j++) {
                int col = c0 + tx * 4 + j;
                float v = acc[i][j] + (bias ? bias[col] : 0.f);
                if (outmode == 1) v = fmaxf(v, 0.f);
                if (outmode == 2)
                    ((__nv_bfloat16*)C)[(size_t)row * N + col] = __float2bfloat16(v);
                else
                    ((float*)C)[(size_t)row * N + col] = v;
            }
        }
    }
}

// ---------------- tensor-core LSTM over degree-uniform batches ----------------
// 6 warps/CTA, each warp = 16 nodes. Whh fragments in smem (128KB).
#define LWARPS 6
#define HSTRIDE 136
#define SM_WF    0
#define SM_BIAS  131072
#define SM_HSTG  133120
#define SM_NID   (SM_HSTG + LWARPS * 16 * HSTRIDE * 2)
#define SM_USM   (SM_NID + LWARPS * 16 * 4)
#define SM_TOTAL (SM_USM + LWARPS * 16 * 4)

__global__ __launch_bounds__(32 * LWARPS, 1)
void lstm_mma(const int* __restrict__ nbr) {
    extern __shared__ char smr[];
    uint2*  wf  = (uint2*)(smr + SM_WF);
    float4* bsm = (float4*)(smr + SM_BIAS);
    __nv_bfloat16* hstg = (__nv_bfloat16*)(smr + SM_HSTG);
    int* nidA = (int*)(smr + SM_NID);
    int* usmA = (int*)(smr + SM_USM);

    int tid = threadIdx.x, wid = tid >> 5, lane = tid & 31;
    for (int i = tid; i < 512 * 32; i += 32 * LWARPS) wf[i] = g_Wfrag[i];
    if (tid < HID) bsm[tid] = g_biasF[tid];
    __syncthreads();

    __nv_bfloat16* hs = hstg + wid * 16 * HSTRIDE;
    int* mynid = nidA + wid * 16;
    int* myu   = usmA + wid * 16;
    int r0 = lane >> 2, q = lane & 3;
    int nb = g_nbatch;
    const __nv_bfloat16* Pp = g_Pb;

    for (int b = blockIdx.x * LWARPS + wid; b < nb; b += gridDim.x * LWARPS) {
        int start = g_batch_start[b];
        int info  = g_batch_info[b];
        int dmax = info >> 8, cnt = info & 255;
        if (lane < 16) mynid[lane] = g_order[start + min(lane, cnt - 1)];
        __syncwarp();

        float cst[64];
#pragma unroll
        for (int i = 0; i < 64; ++i) cst[i] = 0.f;

        for (int t = 0; t < dmax; ++t) {
            if (lane < 16) myu[lane] = nbr[mynid[lane] * MAXD + t];
            __syncwarp();

            unsigned a[8][4];
            if (t > 0) {
#pragma unroll
                for (int kt = 0; kt < 8; ++kt) {
                    const __nv_bfloat16* hb = hs + kt * 16 + q * 2;
                    a[kt][0] = *(const unsigned*)(hb + r0 * HSTRIDE);
                    a[kt][1] = *(const unsigned*)(hb + (r0 + 8) * HSTRIDE);
                    a[kt][2] = *(const unsigned*)(hb + r0 * HSTRIDE + 8);
                    a[kt][3] = *(const unsigned*)(hb + (r0 + 8) * HSTRIDE + 8);
                }
            }
            __syncwarp();   // A reads complete before any lane overwrites hs

            int u_lo = myu[r0], u_hi = myu[r0 + 8];
            const unsigned* PloB = (const unsigned*)(Pp + (size_t)u_lo * 512);
            const unsigned* PhiB = (const unsigned*)(Pp + (size_t)u_hi * 512);
            bool last = (t == dmax - 1);

#pragma unroll
            for (int chunk = 0; chunk < 4; ++chunk) {
                unsigned plo[16], phi[16];
#pragma unroll
                for (int nt = 0; nt < 16; ++nt) {
                    int w = chunk * 64 + nt * 4 + q;   // uint32 index (2 bf16 each)
                    plo[nt] = PloB[w];
                    phi[nt] = PhiB[w];
                }
                float acc[16][4];
#pragma unroll
                for (int nt = 0; nt < 16; ++nt) {
                    acc[nt][0] = 0.f; acc[nt][1] = 0.f; acc[nt][2] = 0.f; acc[nt][3] = 0.f;
                }
                if (t > 0) {
#pragma unroll
                    for (int kt = 0; kt < 8; ++kt) {
#pragma unroll
                        for (int nt = 0; nt < 16; ++nt) {
                            uint2 bb = wf[((kt << 6) + (chunk << 4) + nt) * 32 + lane];
                            mma16816(acc[nt], a[kt], bb.x, bb.y);
                        }
                    }
                }
#pragma unroll
                for (int p = 0; p < 8; ++p) {
                    int J = chunk * 32 + p * 4 + q;
                    float4 bs = bsm[J];
                    // row r0
                    {
                        float gi = acc[2 * p][0]     + blo(plo[2 * p])     + bs.x;
                        float gf = acc[2 * p][1]     + bhi(plo[2 * p])     + bs.y;
                        float gg = acc[2 * p + 1][0] + blo(plo[2 * p + 1]) + bs.z;
                        float go = acc[2 * p + 1][1] + bhi(plo[2 * p + 1]) + bs.w;
                        int ci = chunk * 16 + p * 2;
                        float cn = sigf(gf) * cst[ci] + sigf(gi) * tanh_(gg);
                        cst[ci] = cn;
                        float h = sigf(go) * tanh_(cn);
                        if (!last) hs[r0 * HSTRIDE + J] = __float2bfloat16(h);
                        else if (r0 < cnt) g_hT[(size_t)mynid[r0] * HID + J] = h;
                    }
                    // row r0+8
                    {
                        float gi = acc[2 * p][2]     + blo(phi[2 * p])     + bs.x;
                        float gf = acc[2 * p][3]     + bhi(phi[2 * p])     + bs.y;
                        float gg = acc[2 * p + 1][2] + blo(phi[2 * p + 1]) + bs.z;
                        float go = acc[2 * p + 1][3] + bhi(phi[2 * p + 1]) + bs.w;
                        int ci = chunk * 16 + p * 2 + 1;
                        float cn = sigf(gf) * cst[ci] + sigf(gi) * tanh_(gg);
                        cst[ci] = cn;
                        float h = sigf(go) * tanh_(cn);
                        if (!last) hs[(r0 + 8) * HSTRIDE + J] = __float2bfloat16(h);
                        else if (r0 + 8 < cnt) g_hT[(size_t)mynid[r0 + 8] * HID + J] = h;
                    }
                }
            }
            __syncwarp();   // h stores visible before next step's A loads
        }
    }
}

// ---------------- GraphConv aggregate ----------------
__global__ void agg_kernel(const int* __restrict__ nbr, const int* __restrict__ deg) {
    int wid  = (blockIdx.x * blockDim.x + threadIdx.x) >> 5;
    int lane = threadIdx.x & 31;
    if (wid >= NNODES) return;
    int d = deg[wid];
    const int* nb = nbr + wid * MAXD;
    float4 acc = {0.f, 0.f, 0.f, 0.f};
    for (int t = 0; t < d; ++t) {
        int u = nb[t];
        float nu = rsqrtf((float)max(deg[u], 1));
        float4 v = *(const float4*)(g_h1 + (size_t)u * 128 + lane * 4);
        acc.x = fmaf(v.x, nu, acc.x); acc.y = fmaf(v.y, nu, acc.y);
        acc.z = fmaf(v.z, nu, acc.z); acc.w = fmaf(v.w, nu, acc.w);
    }
    float nn = rsqrtf((float)max(d, 1));
    float4 o = {acc.x * nn, acc.y * nn, acc.z * nn, acc.w * nn};
    *(float4*)(g_agg + (size_t)wid * 128 + lane * 4) = o;
}

// ---------------- GRU ----------------
__global__ void gru_kernel(const float* __restrict__ bih, const float* __restrict__ bhh) {
    extern __shared__ char sm[];
    float4* Wt   = (float4*)sm;
    float*  hrow = (float*)(sm + 65536);
    int tid = threadIdx.x;
    for (int i = tid; i < HID * GRUH; i += blockDim.x) Wt[i] = g_Wt3[i];
    __syncthreads();

    int w = tid >> 5, lane = tid & 31;
    float br = bih[lane], bz = bih[32 + lane], bn = bih[64 + lane];
    float cr = bhh[lane], cz = bhh[32 + lane], cnb = bhh[64 + lane];
    float* hr = hrow + w * 128;
    int nwarp = gridDim.x * 8;
    for (int node = blockIdx.x * 8 + w; node < NNODES; node += nwarp) {
        const float* h2 = g_h2 + (size_t)node * 128;
        *(float4*)(hr + lane * 4) = *(const float4*)(h2 + lane * 4);
        __syncwarp();
        float ar = 0.f, az = 0.f, an = 0.f;
#pragma unroll 8
        for (int k = 0; k < 128; ++k) {
            float hk = hr[k];
            float4 wv = Wt[k * 32 + lane];
            ar = fmaf(hk, wv.x, ar);
            az = fmaf(hk, wv.y, az);
            an = fmaf(hk, wv.z, an);
        }
        __syncwarp();
        float r   = sigf(ar + br + cr);
        float z   = sigf(az + bz + cz);
        float nst = tanh_(an + bn + r * cnb);
        g_o32[(size_t)node * 32 + lane] = (1.f - z) * nst;
    }
}

// ---------------- mean pool + classifier ----------------
__global__ void pool_kernel(const int* __restrict__ gid,
                            const float* __restrict__ Wc,
                            const float* __restrict__ bc,
                            float* __restrict__ out) {
    __shared__ float s[8][32];
    __shared__ int   scnt[8];
    __shared__ float hg[32];
    int g = blockIdx.x;
    int tid = threadIdx.x, lane = tid & 31, slot = tid >> 5;
    float acc = 0.f;
    int cnt = 0;
    for (int i = slot; i < NNODES; i += 8) {
        if (gid[i] == g) {
            acc += g_o32[(size_t)i * 32 + lane];
            cnt++;
        }
    }
    s[slot][lane] = acc;
    if (lane == 0) scnt[slot] = cnt;
    __syncthreads();
    if (tid < 32) {
        float sum = 0.f; int tot = 0;
#pragma unroll
        for (int j = 0; j < 8; ++j) { sum += s[j][tid]; tot += scnt[j]; }
        hg[tid] = sum / (float)tot;
    }
    __syncthreads();
    if (tid < NCLS) {
        float o = bc[tid];
#pragma unroll
        for (int k = 0; k < 32; ++k) o = fmaf(hg[k], Wc[k * NCLS + tid], o);
        out[g * NCLS + tid] = o;
    }
}

// ---------------- launch ----------------
extern "C" void kernel_launch(void* const* d_in, const int* in_sizes, int n_in,
                              void* d_out, int out_size) {
    const float* feature = (const float*)d_in[0];
    const int*   nbr     = (const int*)  d_in[1];
    const int*   deg     = (const int*)  d_in[2];
    const int*   gid     = (const int*)  d_in[3];
    const float* lWih    = (const float*)d_in[4];
    const float* lWhh    = (const float*)d_in[5];
    const float* lbih    = (const float*)d_in[6];
    const float* lbhh    = (const float*)d_in[7];
    const float* Wself   = (const float*)d_in[8];
    const float* Wneigh  = (const float*)d_in[9];
    const float* bsage   = (const float*)d_in[10];
    const float* Wgc     = (const float*)d_in[11];
    const float* bgc     = (const float*)d_in[12];
    const float* Wgru    = (const float*)d_in[13];
    const float* bihg    = (const float*)d_in[14];
    const float* bhhg    = (const float*)d_in[15];
    const float* Wcls    = (const float*)d_in[16];
    const float* bcls    = (const float*)d_in[17];
    float* out = (float*)d_out;

    cudaFuncSetAttribute(lstm_mma, cudaFuncAttributeMaxDynamicSharedMemorySize, SM_TOTAL);
    cudaFuncSetAttribute(gru_kernel, cudaFuncAttributeMaxDynamicSharedMemorySize, 69632 + 256);

    void *pPb, *pWihTp, *phT, *ph1, *pagg, *ph2;
    cudaGetSymbolAddress(&pPb,    g_Pb);
    cudaGetSymbolAddress(&pWihTp, g_WihTp);
    cudaGetSymbolAddress(&phT,    g_hT);
    cudaGetSymbolAddress(&ph1,    g_h1);
    cudaGetSymbolAddress(&pagg,   g_agg);
    cudaGetSymbolAddress(&ph2,    g_h2);

    prep_kernel<<<256, 256>>>(lWih, lWhh, lbih, lbhh, Wgru);

    // degree bucketing
    k_zero<<<1, 32>>>();
    k_hist<<<98, 512>>>(deg);
    k_batches<<<1, 32>>>();
    k_scatter<<<(NNODES + 511) / 512, 512>>>(deg);

    // P = feature @ WihT_perm   -> bf16 permuted [N,512]
    {
        dim3 grid((NNODES + 63) / 64, 512 / 64);
        gemm128<<<grid, 256>>>(feature, (const float*)pWihTp, nullptr, nullptr,
                               nullptr, pPb, NNODES, 512, 2);
    }
    // tensor-core LSTM
    lstm_mma<<<152, 32 * LWARPS, SM_TOTAL>>>(nbr);
    // h1 = relu(feature@W_self + hT@W_neigh + b_sage)
    {
        dim3 grid((NNODES + 63) / 64, 128 / 64);
        gemm128<<<grid, 256>>>(feature, Wself, (const float*)phT, Wneigh,
                               bsage, ph1, NNODES, 128, 1);
    }
    agg_kernel<<<(NNODES * 32 + 255) / 256, 256>>>(nbr, deg);
    {
        dim3 grid((NNODES + 63) / 64, 128 / 64);
        gemm128<<<grid, 256>>>((const float*)pagg, Wgc, nullptr, nullptr,
                               bgc, ph2, NNODES, 128, 1);
    }
    gru_kernel<<<304, 256, 69632 + 256>>>(bihg, bhhg);
    pool_kernel<<<NGRAPH, 256>>>(gid, Wcls, bcls, out);
}

// round 3
// speedup vs baseline: 2.4113x; 1.2577x over previous
#include <cuda_runtime.h>
#include <cuda_bf16.h>
#include <cstdint>

#define NNODES 50000
#define HID    128
#define MAXD   16
#define NGRAPH 50
#define NCLS   10
#define GRUH   32
#define MAXB   3400

// ---------------- scratch ----------------
__device__ __nv_bfloat16 g_Pb [(size_t)NNODES * 512]; // feature@WihT, bf16, phys-permuted cols
__device__ float g_hT [(size_t)NNODES * HID];
__device__ float g_h1 [(size_t)NNODES * HID];
__device__ float g_agg[(size_t)NNODES * HID];
__device__ float g_h2 [(size_t)NNODES * HID];
__device__ float g_o32[(size_t)NNODES * GRUH];
__device__ float g_WihTp[HID * 512];         // [k][p] permuted
__device__ uint2 g_Wfrag[512 * 32];          // Whh fragments: tile(kt*64+ntg) x lane
__device__ float4 g_biasF[HID];              // (bi,bf,bg,bo) per hidden j
__device__ float4 g_Wt3 [HID * GRUH];        // GRU
// degree bucketing
__device__ int g_order[NNODES];
__device__ int g_bincnt[16];
__device__ int g_binoff[16];
__device__ int g_batch_start[MAXB];
__device__ int g_batch_info[MAXB];           // (deg<<8)|cnt
__device__ int g_nbatch;

// ---------------- helpers ----------------
__device__ __forceinline__ float sigf(float x) {
    x = fminf(fmaxf(x, -30.f), 30.f);
    return __fdividef(1.f, 1.f + __expf(-x));
}
__device__ __forceinline__ float tanh_(float x) {
    x = fminf(fmaxf(x, -15.f), 15.f);
    float e = __expf(-2.f * x);
    return __fdividef(1.f - e, 1.f + e);
}
__device__ __forceinline__ float tanhap(float x) {
    float y;
    asm("tanh.approx.f32 %0, %1;" : "=f"(y) : "f"(x));
    return y;
}
__device__ __forceinline__ float sigt(float x) {
    return fmaf(tanhap(x * 0.5f), 0.5f, 0.5f);
}
__device__ __forceinline__ unsigned bf16u(float x) {
    __nv_bfloat16 b = __float2bfloat16(x);
    return (unsigned)*reinterpret_cast<unsigned short*>(&b);
}
__device__ __forceinline__ float blo(unsigned v) { return __uint_as_float(v << 16); }
__device__ __forceinline__ float bhi(unsigned v) { return __uint_as_float(v & 0xFFFF0000u); }

// phys col p -> logical LSTM row (gamma*128+j)
__host__ __device__ __forceinline__ int phys2row(int p) {
    int pb = p >> 4, rem = p & 15;
    int gamma, aa;
    if (rem < 8) { aa = rem >> 1; gamma = (rem & 1) ? 1 : 0; }
    else         { aa = (rem - 8) >> 1; gamma = (rem & 1) ? 3 : 2; }
    return gamma * HID + pb * 4 + aa;
}

__device__ __forceinline__ void mma16816(float* d, const unsigned* a, unsigned b0, unsigned b1) {
    asm volatile(
        "mma.sync.aligned.m16n8k16.row.col.f32.bf16.bf16.f32 "
        "{%0,%1,%2,%3}, {%4,%5,%6,%7}, {%8,%9}, {%0,%1,%2,%3};"
        : "+f"(d[0]), "+f"(d[1]), "+f"(d[2]), "+f"(d[3])
        : "r"(a[0]), "r"(a[1]), "r"(a[2]), "r"(a[3]), "r"(b0), "r"(b1));
}

// ---------------- prep: packing / transposes ----------------
__global__ void prep_kernel(const float* __restrict__ Wih,
                            const float* __restrict__ Whh,
                            const float* __restrict__ bih,
                            const float* __restrict__ bhh,
                            const float* __restrict__ Wgru) {
    int idx = blockIdx.x * blockDim.x + threadIdx.x;
    if (idx < HID * 512) {
        int k = idx >> 9, p = idx & 511;
        g_WihTp[idx] = Wih[phys2row(p) * HID + k];
    }
    if (idx < 512 * 32) {
        int t_id = idx >> 5, lane = idx & 31;
        int kt = t_id >> 6, ntg = t_id & 63;
        int p = ntg * 8 + (lane >> 2);
        int wrow = phys2row(p);
        int k0 = kt * 16 + (lane & 3) * 2;
        const float* wr = Whh + (size_t)wrow * HID;
        uint2 v;
        v.x = bf16u(wr[k0])     | (bf16u(wr[k0 + 1]) << 16);
        v.y = bf16u(wr[k0 + 8]) | (bf16u(wr[k0 + 9]) << 16);
        g_Wfrag[idx] = v;
    }
    if (idx < HID) {
        g_biasF[idx] = make_float4(bih[idx] + bhh[idx],
                                   bih[HID + idx] + bhh[HID + idx],
                                   bih[2 * HID + idx] + bhh[2 * HID + idx],
                                   bih[3 * HID + idx] + bhh[3 * HID + idx]);
    }
    if (idx < HID * GRUH) {
        int k = idx >> 5, l = idx & 31;
        g_Wt3[idx] = make_float4(Wgru[(0 * GRUH + l) * HID + k],
                                 Wgru[(1 * GRUH + l) * HID + k],
                                 Wgru[(2 * GRUH + l) * HID + k], 0.f);
    }
}

// ---------------- degree bucketing ----------------
__global__ void k_zero() {
    if (threadIdx.x < 16) g_bincnt[threadIdx.x] = 0;
}
__global__ void k_hist(const int* __restrict__ deg) {
    __shared__ int h[16];
    if (threadIdx.x < 16) h[threadIdx.x] = 0;
    __syncthreads();
    for (int i = blockIdx.x * blockDim.x + threadIdx.x; i < NNODES; i += gridDim.x * blockDim.x)
        atomicAdd(&h[deg[i] - 1], 1);
    __syncthreads();
    if (threadIdx.x < 16) atomicAdd(&g_bincnt[threadIdx.x], h[threadIdx.x]);
}
__global__ void k_batches() {
    __shared__ int bstart[16], boff[16];
    if (threadIdx.x == 0) {
        int off = 0, bo = 0;
        for (int d = 0; d < 16; ++d) {
            bstart[d] = off; g_binoff[d] = off; boff[d] = bo;
            off += g_bincnt[d];
            bo += (g_bincnt[d] + 15) >> 4;
        }
        g_nbatch = bo;
    }
    __syncthreads();
    int d = threadIdx.x;
    if (d < 16) {
        int cnt = g_bincnt[d];
        int bi = boff[d];
        for (int j = 0; j < cnt; j += 16, ++bi) {
            g_batch_start[bi] = bstart[d] + j;
            g_batch_info[bi]  = ((d + 1) << 8) | min(16, cnt - j);
        }
    }
}
__global__ void k_scatter(const int* __restrict__ deg) {
    __shared__ int scnt[16], sbase[16], scur[16];
    int t = threadIdx.x;
    if (t < 16) { scnt[t] = 0; scur[t] = 0; }
    __syncthreads();
    int i = blockIdx.x * 512 + t;
    int d = -1;
    if (i < NNODES) { d = deg[i] - 1; atomicAdd(&scnt[d], 1); }
    __syncthreads();
    if (t < 16 && scnt[t] > 0) sbase[t] = atomicAdd(&g_binoff[t], scnt[t]);
    __syncthreads();
    if (i < NNODES) {
        int pos = sbase[d] + atomicAdd(&scur[d], 1);
        g_order[pos] = i;
    }
}

// ---------------- generic K=128 GEMM ----------------
__global__ void gemm128(const float* __restrict__ A,  const float* __restrict__ W,
                        const float* __restrict__ A2, const float* __restrict__ W2,
                        const float* __restrict__ bias, void* __restrict__ C,
                        int M, int N, int outmode) {
    __shared__ float Asm[32][68];
    __shared__ float Wsm[32][64];
    int tid = threadIdx.x;
    int tx = tid & 15, ty = tid >> 4;
    int r0 = blockIdx.x * 64, c0 = blockIdx.y * 64;

    float acc[4][4];
#pragma unroll
    for (int i = 0; i < 4; i++)
#pragma unroll
        for (int j = 0; j < 4; j++) acc[i][j] = 0.f;

    int npass = (A2 != nullptr) ? 2 : 1;
    for (int p = 0; p < npass; ++p) {
        const float* Ap = p ? A2 : A;
        const float* Wp = p ? W2 : W;
        for (int kk = 0; kk < 128; kk += 32) {
            __syncthreads();
            {
                int k = tid & 31, r = tid >> 5;
#pragma unroll
                for (int pp = 0; pp < 8; ++pp) {
                    int row = r0 + r + pp * 8;
                    row = min(row, M - 1);
                    Asm[k][r + pp * 8] = Ap[(size_t)row * 128 + kk + k];
                }
            }
            {
                int c = tid & 63, kq = tid >> 6;
#pragma unroll
                for (int pp = 0; pp < 8; ++pp)
                    Wsm[kq + pp * 4][c] = Wp[(size_t)(kk + kq + pp * 4) * N + c0 + c];
            }
            __syncthreads();
#pragma unroll
            for (int k = 0; k < 32; ++k) {
                float4 a4 = *(const float4*)&Asm[k][ty * 4];
                float4 w4 = *(const float4*)&Wsm[k][tx * 4];
                float ar[4] = {a4.x, a4.y, a4.z, a4.w};
                float wc[4] = {w4.x, w4.y, w4.z, w4.w};
#pragma unroll
                for (int i = 0; i < 4; i++)
#pragma unroll
                    for (int j = 0; j < 4; j++)
                        acc[i][j] = fmaf(ar[i], wc[j], acc[i][j]);
            }
        }
    }
#pragma unroll
    for (int i = 0; i < 4; i++) {
        int row = r0 + ty * 4 + i;
        if (row < M) {
#pragma unroll
            for (int j = 0; j < 4; j++) {
                int col = c0 + tx * 4 + j;
                float v = acc[i][j] + (bias ? bias[col] : 0.f);
                if (outmode == 1) v = fmaxf(v, 0.f);
                if (outmode == 2)
                    ((__nv_bfloat16*)C)[(size_t)row * N + col] = __float2bfloat16(v);
                else
                    ((float*)C)[(size_t)row * N + col] = v;
            }
        }
    }
}

// ---------------- tensor-core LSTM: 4-warp groups, 2 groups/CTA ----------------
#define LGROUPS 2
#define HSTRIDE 136
#define SM_WF    0
#define SM_BIAS  131072
#define SM_HSTG  133120
#define SM_NID   (SM_HSTG + LGROUPS * 16 * HSTRIDE * 2)
#define SM_USM   (SM_NID + LGROUPS * 64)
#define SM_TOTAL (SM_USM + LGROUPS * 64)

__global__ __launch_bounds__(256, 1)
void lstm_mma(const int* __restrict__ nbr) {
    extern __shared__ char smr[];
    uint2*  wf  = (uint2*)(smr + SM_WF);
    float4* bsm = (float4*)(smr + SM_BIAS);
    __nv_bfloat16* hstg = (__nv_bfloat16*)(smr + SM_HSTG);
    int* nidA = (int*)(smr + SM_NID);
    int* usmA = (int*)(smr + SM_USM);

    int tid = threadIdx.x, wid = tid >> 5, lane = tid & 31;
    for (int i = tid; i < 512 * 32; i += 256) wf[i] = g_Wfrag[i];
    if (tid < HID) bsm[tid] = g_biasF[tid];
    __syncthreads();

    int grp = wid >> 2;        // 0..1
    int chunk = wid & 3;       // gate-column chunk this warp owns
    __nv_bfloat16* hs = hstg + grp * 16 * HSTRIDE;
    int* mynid = nidA + grp * 16;
    int* myu   = usmA + grp * 16;
    int r0 = lane >> 2, q = lane & 3;
    int barid = grp + 1;
    int nb = g_nbatch;
    const __nv_bfloat16* Pp = g_Pb;

    for (int b = blockIdx.x * LGROUPS + grp; b < nb; b += gridDim.x * LGROUPS) {
        // protect mynid against stragglers of the previous batch
        asm volatile("bar.sync %0, %1;" :: "r"(barid), "r"(128) : "memory");
        int start = g_batch_start[b];
        int info  = g_batch_info[b];
        int dmax = info >> 8, cnt = info & 255;
        if (chunk == 0 && lane < 16) mynid[lane] = g_order[start + min(lane, cnt - 1)];

        float cst[16];
#pragma unroll
        for (int i = 0; i < 16; ++i) cst[i] = 0.f;

        for (int t = 0; t < dmax; ++t) {
            if (chunk == 0 && lane < 16) myu[lane] = nbr[mynid[lane] * MAXD + t];
            // publish myu (+mynid at t=0); prev-step h writes visible
            asm volatile("bar.sync %0, %1;" :: "r"(barid), "r"(128) : "memory");

            unsigned a[8][4];
            if (t > 0) {
#pragma unroll
                for (int kt = 0; kt < 8; ++kt) {
                    const __nv_bfloat16* hb = hs + kt * 16 + q * 2;
                    a[kt][0] = *(const unsigned*)(hb + r0 * HSTRIDE);
                    a[kt][1] = *(const unsigned*)(hb + (r0 + 8) * HSTRIDE);
                    a[kt][2] = *(const unsigned*)(hb + r0 * HSTRIDE + 8);
                    a[kt][3] = *(const unsigned*)(hb + (r0 + 8) * HSTRIDE + 8);
                }
            }
            int u_lo = myu[r0], u_hi = myu[r0 + 8];
            const unsigned* PloB = (const unsigned*)(Pp + (size_t)u_lo * 512);
            const unsigned* PhiB = (const unsigned*)(Pp + (size_t)u_hi * 512);
            unsigned plo[16], phi[16];
#pragma unroll
            for (int nt = 0; nt < 16; ++nt) {
                int w = chunk * 64 + nt * 4 + q;
                plo[nt] = PloB[w];
                phi[nt] = PhiB[w];
            }
            // all hs reads done before epilogue overwrites
            asm volatile("bar.sync %0, %1;" :: "r"(barid), "r"(128) : "memory");

            float acc[16][4];
#pragma unroll
            for (int nt = 0; nt < 16; ++nt) {
                acc[nt][0] = 0.f; acc[nt][1] = 0.f; acc[nt][2] = 0.f; acc[nt][3] = 0.f;
            }
            if (t > 0) {
#pragma unroll
                for (int kt = 0; kt < 8; ++kt) {
#pragma unroll
                    for (int nt = 0; nt < 16; ++nt) {
                        uint2 bb = wf[((kt << 6) + (chunk << 4) + nt) * 32 + lane];
                        mma16816(acc[nt], a[kt], bb.x, bb.y);
                    }
                }
            }
            bool last = (t == dmax - 1);
#pragma unroll
            for (int p = 0; p < 8; ++p) {
                int J = chunk * 32 + p * 4 + q;
                float4 bs = bsm[J];
                {   // row r0
                    float gi = acc[2 * p][0]     + blo(plo[2 * p])     + bs.x;
                    float gf = acc[2 * p][1]     + bhi(plo[2 * p])     + bs.y;
                    float gg = acc[2 * p + 1][0] + blo(plo[2 * p + 1]) + bs.z;
                    float go = acc[2 * p + 1][1] + bhi(plo[2 * p + 1]) + bs.w;
                    float cn = sigt(gf) * cst[2 * p] + sigt(gi) * tanhap(gg);
                    cst[2 * p] = cn;
                    float h = sigt(go) * tanhap(cn);
                    if (!last) hs[r0 * HSTRIDE + J] = __float2bfloat16(h);
                    else if (r0 < cnt) g_hT[(size_t)mynid[r0] * HID + J] = h;
                }
                {   // row r0+8
                    float gi = acc[2 * p][2]     + blo(phi[2 * p])     + bs.x;
                    float gf = acc[2 * p][3]     + bhi(phi[2 * p])     + bs.y;
                    float gg = acc[2 * p + 1][2] + blo(phi[2 * p + 1]) + bs.z;
                    float go = acc[2 * p + 1][3] + bhi(phi[2 * p + 1]) + bs.w;
                    float cn = sigt(gf) * cst[2 * p + 1] + sigt(gi) * tanhap(gg);
                    cst[2 * p + 1] = cn;
                    float h = sigt(go) * tanhap(cn);
                    if (!last) hs[(r0 + 8) * HSTRIDE + J] = __float2bfloat16(h);
                    else if (r0 + 8 < cnt) g_hT[(size_t)mynid[r0 + 8] * HID + J] = h;
                }
            }
        }
    }
}

// ---------------- GraphConv aggregate ----------------
__global__ void agg_kernel(const int* __restrict__ nbr, const int* __restrict__ deg) {
    int wid  = (blockIdx.x * blockDim.x + threadIdx.x) >> 5;
    int lane = threadIdx.x & 31;
    if (wid >= NNODES) return;
    int d = deg[wid];
    const int* nb = nbr + wid * MAXD;
    float4 acc = {0.f, 0.f, 0.f, 0.f};
    for (int t = 0; t < d; ++t) {
        int u = nb[t];
        float nu = rsqrtf((float)max(deg[u], 1));
        float4 v = *(const float4*)(g_h1 + (size_t)u * 128 + lane * 4);
        acc.x = fmaf(v.x, nu, acc.x); acc.y = fmaf(v.y, nu, acc.y);
        acc.z = fmaf(v.z, nu, acc.z); acc.w = fmaf(v.w, nu, acc.w);
    }
    float nn = rsqrtf((float)max(d, 1));
    float4 o = {acc.x * nn, acc.y * nn, acc.z * nn, acc.w * nn};
    *(float4*)(g_agg + (size_t)wid * 128 + lane * 4) = o;
}

// ---------------- GRU ----------------
__global__ void gru_kernel(const float* __restrict__ bih, const float* __restrict__ bhh) {
    extern __shared__ char sm[];
    float4* Wt   = (float4*)sm;
    float*  hrow = (float*)(sm + 65536);
    int tid = threadIdx.x;
    for (int i = tid; i < HID * GRUH; i += blockDim.x) Wt[i] = g_Wt3[i];
    __syncthreads();

    int w = tid >> 5, lane = tid & 31;
    float br = bih[lane], bz = bih[32 + lane], bn = bih[64 + lane];
    float cr = bhh[lane], cz = bhh[32 + lane], cnb = bhh[64 + lane];
    float* hr = hrow + w * 128;
    int nwarp = gridDim.x * 8;
    for (int node = blockIdx.x * 8 + w; node < NNODES; node += nwarp) {
        const float* h2 = g_h2 + (size_t)node * 128;
        *(float4*)(hr + lane * 4) = *(const float4*)(h2 + lane * 4);
        __syncwarp();
        float ar = 0.f, az = 0.f, an = 0.f;
#pragma unroll 8
        for (int k = 0; k < 128; ++k) {
            float hk = hr[k];
            float4 wv = Wt[k * 32 + lane];
            ar = fmaf(hk, wv.x, ar);
            az = fmaf(hk, wv.y, az);
            an = fmaf(hk, wv.z, an);
        }
        __syncwarp();
        float r   = sigf(ar + br + cr);
        float z   = sigf(az + bz + cz);
        float nst = tanh_(an + bn + r * cnb);
        g_o32[(size_t)node * 32 + lane] = (1.f - z) * nst;
    }
}

// ---------------- mean pool + classifier ----------------
__global__ void pool_kernel(const int* __restrict__ gid,
                            const float* __restrict__ Wc,
                            const float* __restrict__ bc,
                            float* __restrict__ out) {
    __shared__ float s[8][32];
    __shared__ int   scnt[8];
    __shared__ float hg[32];
    int g = blockIdx.x;
    int tid = threadIdx.x, lane = tid & 31, slot = tid >> 5;
    float acc = 0.f;
    int cnt = 0;
    for (int i = slot; i < NNODES; i += 8) {
        if (gid[i] == g) {
            acc += g_o32[(size_t)i * 32 + lane];
            cnt++;
        }
    }
    s[slot][lane] = acc;
    if (lane == 0) scnt[slot] = cnt;
    __syncthreads();
    if (tid < 32) {
        float sum = 0.f; int tot = 0;
#pragma unroll
        for (int j = 0; j < 8; ++j) { sum += s[j][tid]; tot += scnt[j]; }
        hg[tid] = sum / (float)tot;
    }
    __syncthreads();
    if (tid < NCLS) {
        float o = bc[tid];
#pragma unroll
        for (int k = 0; k < 32; ++k) o = fmaf(hg[k], Wc[k * NCLS + tid], o);
        out[g * NCLS + tid] = o;
    }
}

// ---------------- launch ----------------
extern "C" void kernel_launch(void* const* d_in, const int* in_sizes, int n_in,
                              void* d_out, int out_size) {
    const float* feature = (const float*)d_in[0];
    const int*   nbr     = (const int*)  d_in[1];
    const int*   deg     = (const int*)  d_in[2];
    const int*   gid     = (const int*)  d_in[3];
    const float* lWih    = (const float*)d_in[4];
    const float* lWhh    = (const float*)d_in[5];
    const float* lbih    = (const float*)d_in[6];
    const float* lbhh    = (const float*)d_in[7];
    const float* Wself   = (const float*)d_in[8];
    const float* Wneigh  = (const float*)d_in[9];
    const float* bsage   = (const float*)d_in[10];
    const float* Wgc     = (const float*)d_in[11];
    const float* bgc     = (const float*)d_in[12];
    const float* Wgru    = (const float*)d_in[13];
    const float* bihg    = (const float*)d_in[14];
    const float* bhhg    = (const float*)d_in[15];
    const float* Wcls    = (const float*)d_in[16];
    const float* bcls    = (const float*)d_in[17];
    float* out = (float*)d_out;

    cudaFuncSetAttribute(lstm_mma, cudaFuncAttributeMaxDynamicSharedMemorySize, SM_TOTAL);
    cudaFuncSetAttribute(gru_kernel, cudaFuncAttributeMaxDynamicSharedMemorySize, 69632 + 256);

    void *pPb, *pWihTp, *phT, *ph1, *pagg, *ph2;
    cudaGetSymbolAddress(&pPb,    g_Pb);
    cudaGetSymbolAddress(&pWihTp, g_WihTp);
    cudaGetSymbolAddress(&phT,    g_hT);
    cudaGetSymbolAddress(&ph1,    g_h1);
    cudaGetSymbolAddress(&pagg,   g_agg);
    cudaGetSymbolAddress(&ph2,    g_h2);

    prep_kernel<<<256, 256>>>(lWih, lWhh, lbih, lbhh, Wgru);

    k_zero<<<1, 32>>>();
    k_hist<<<98, 512>>>(deg);
    k_batches<<<1, 32>>>();
    k_scatter<<<(NNODES + 511) / 512, 512>>>(deg);

    // P = feature @ WihT_perm -> bf16 permuted [N,512]
    {
        dim3 grid((NNODES + 63) / 64, 512 / 64);
        gemm128<<<grid, 256>>>(feature, (const float*)pWihTp, nullptr, nullptr,
                               nullptr, pPb, NNODES, 512, 2);
    }
    // tensor-core LSTM
    lstm_mma<<<152, 256, SM_TOTAL>>>(nbr);
    // h1 = relu(feature@W_self + hT@W_neigh + b_sage)
    {
        dim3 grid((NNODES + 63) / 64, 128 / 64);
        gemm128<<<grid, 256>>>(feature, Wself, (const float*)phT, Wneigh,
                               bsage, ph1, NNODES, 128, 1);
    }
    agg_kernel<<<(NNODES * 32 + 255) / 256, 256>>>(nbr, deg);
    {
        dim3 grid((NNODES + 63) / 64, 128 / 64);
        gemm128<<<grid, 256>>>((const float*)pagg, Wgc, nullptr, nullptr,
                               bgc, ph2, NNODES, 128, 1);
    }
    gru_kernel<<<304, 256, 69632 + 256>>>(bihg, bhhg);
    pool_kernel<<<NGRAPH, 256>>>(gid, Wcls, bcls, out);
}

// round 4
// speedup vs baseline: 2.5365x; 1.0519x over previous
#include <cuda_runtime.h>
#include <cuda_bf16.h>
#include <cstdint>

#define NNODES 50000
#define HID    128
#define MAXD   16
#define NGRAPH 50
#define NCLS   10
#define GRUH   32
#define MAXB   3400

// ---------------- scratch ----------------
__device__ __nv_bfloat16 g_Pb [(size_t)NNODES * 512]; // feature@WihT, bf16, phys-permuted cols
__device__ float g_hT [(size_t)NNODES * HID];
__device__ float g_h1 [(size_t)NNODES * HID];
__device__ float g_agg[(size_t)NNODES * HID];
__device__ float g_h2 [(size_t)NNODES * HID];
__device__ float g_o32[(size_t)NNODES * GRUH];
__device__ float g_WihTp[HID * 512];         // [k][p] permuted
__device__ uint2 g_Wfrag[512 * 32];          // Whh fragments
__device__ float4 g_biasF[HID];              // (bi,bf,bg,bo)
__device__ float4 g_Wt3 [HID * GRUH];        // GRU
// degree bucketing
__device__ int g_order[NNODES];
__device__ int g_bincnt[16];
__device__ int g_binoff[16];
__device__ int g_batch_start[MAXB];
__device__ int g_batch_info[MAXB];           // (deg<<8)|cnt
__device__ int g_nbatch;

// ---------------- helpers ----------------
__device__ __forceinline__ float sigf(float x) {
    x = fminf(fmaxf(x, -30.f), 30.f);
    return __fdividef(1.f, 1.f + __expf(-x));
}
__device__ __forceinline__ float tanh_(float x) {
    x = fminf(fmaxf(x, -15.f), 15.f);
    float e = __expf(-2.f * x);
    return __fdividef(1.f - e, 1.f + e);
}
__device__ __forceinline__ float tanhap(float x) {
    float y;
    asm("tanh.approx.f32 %0, %1;" : "=f"(y) : "f"(x));
    return y;
}
__device__ __forceinline__ float sigt(float x) {
    return fmaf(tanhap(x * 0.5f), 0.5f, 0.5f);
}
__device__ __forceinline__ unsigned bf16u(float x) {
    __nv_bfloat16 b = __float2bfloat16(x);
    return (unsigned)*reinterpret_cast<unsigned short*>(&b);
}
__device__ __forceinline__ float blo(unsigned v) { return __uint_as_float(v << 16); }
__device__ __forceinline__ float bhi(unsigned v) { return __uint_as_float(v & 0xFFFF0000u); }

// phys col p -> logical LSTM row (gamma*128+j)
__host__ __device__ __forceinline__ int phys2row(int p) {
    int pb = p >> 4, rem = p & 15;
    int gamma, aa;
    if (rem < 8) { aa = rem >> 1; gamma = (rem & 1) ? 1 : 0; }
    else         { aa = (rem - 8) >> 1; gamma = (rem & 1) ? 3 : 2; }
    return gamma * HID + pb * 4 + aa;
}

__device__ __forceinline__ void mma16816(float* d, const unsigned* a, unsigned b0, unsigned b1) {
    asm volatile(
        "mma.sync.aligned.m16n8k16.row.col.f32.bf16.bf16.f32 "
        "{%0,%1,%2,%3}, {%4,%5,%6,%7}, {%8,%9}, {%0,%1,%2,%3};"
        : "+f"(d[0]), "+f"(d[1]), "+f"(d[2]), "+f"(d[3])
        : "r"(a[0]), "r"(a[1]), "r"(a[2]), "r"(a[3]), "r"(b0), "r"(b1));
}

// ---------------- prep ----------------
__global__ void prep_kernel(const float* __restrict__ Wih,
                            const float* __restrict__ Whh,
                            const float* __restrict__ bih,
                            const float* __restrict__ bhh,
                            const float* __restrict__ Wgru) {
    int idx = blockIdx.x * blockDim.x + threadIdx.x;
    if (idx < HID * 512) {
        int k = idx >> 9, p = idx & 511;
        g_WihTp[idx] = Wih[phys2row(p) * HID + k];
    }
    if (idx < 512 * 32) {
        int t_id = idx >> 5, lane = idx & 31;
        int kt = t_id >> 6, ntg = t_id & 63;
        int p = ntg * 8 + (lane >> 2);
        int wrow = phys2row(p);
        int k0 = kt * 16 + (lane & 3) * 2;
        const float* wr = Whh + (size_t)wrow * HID;
        uint2 v;
        v.x = bf16u(wr[k0])     | (bf16u(wr[k0 + 1]) << 16);
        v.y = bf16u(wr[k0 + 8]) | (bf16u(wr[k0 + 9]) << 16);
        g_Wfrag[idx] = v;
    }
    if (idx < HID) {
        g_biasF[idx] = make_float4(bih[idx] + bhh[idx],
                                   bih[HID + idx] + bhh[HID + idx],
                                   bih[2 * HID + idx] + bhh[2 * HID + idx],
                                   bih[3 * HID + idx] + bhh[3 * HID + idx]);
    }
    if (idx < HID * GRUH) {
        int k = idx >> 5, l = idx & 31;
        g_Wt3[idx] = make_float4(Wgru[(0 * GRUH + l) * HID + k],
                                 Wgru[(1 * GRUH + l) * HID + k],
                                 Wgru[(2 * GRUH + l) * HID + k], 0.f);
    }
}

// ---------------- degree bucketing ----------------
__global__ void k_zero() {
    if (threadIdx.x < 16) g_bincnt[threadIdx.x] = 0;
}
__global__ void k_hist(const int* __restrict__ deg) {
    __shared__ int h[16];
    if (threadIdx.x < 16) h[threadIdx.x] = 0;
    __syncthreads();
    for (int i = blockIdx.x * blockDim.x + threadIdx.x; i < NNODES; i += gridDim.x * blockDim.x)
        atomicAdd(&h[deg[i] - 1], 1);
    __syncthreads();
    if (threadIdx.x < 16) atomicAdd(&g_bincnt[threadIdx.x], h[threadIdx.x]);
}
__global__ void k_batches() {
    __shared__ int bstart[16], boff[16];
    if (threadIdx.x == 0) {
        int off = 0, bo = 0;
        for (int d = 0; d < 16; ++d) {
            bstart[d] = off; g_binoff[d] = off; boff[d] = bo;
            off += g_bincnt[d];
            bo += (g_bincnt[d] + 15) >> 4;
        }
        g_nbatch = bo;
    }
    __syncthreads();
    int d = threadIdx.x;
    if (d < 16) {
        int cnt = g_bincnt[d];
        int bi = boff[d];
        for (int j = 0; j < cnt; j += 16, ++bi) {
            g_batch_start[bi] = bstart[d] + j;
            g_batch_info[bi]  = ((d + 1) << 8) | min(16, cnt - j);
        }
    }
}
__global__ void k_scatter(const int* __restrict__ deg) {
    __shared__ int scnt[16], sbase[16], scur[16];
    int t = threadIdx.x;
    if (t < 16) { scnt[t] = 0; scur[t] = 0; }
    __syncthreads();
    int i = blockIdx.x * 512 + t;
    int d = -1;
    if (i < NNODES) { d = deg[i] - 1; atomicAdd(&scnt[d], 1); }
    __syncthreads();
    if (t < 16 && scnt[t] > 0) sbase[t] = atomicAdd(&g_binoff[t], scnt[t]);
    __syncthreads();
    if (i < NNODES) {
        int pos = sbase[d] + atomicAdd(&scur[d], 1);
        g_order[pos] = i;
    }
}

// ---------------- generic K=128 GEMM ----------------
__global__ void gemm128(const float* __restrict__ A,  const float* __restrict__ W,
                        const float* __restrict__ A2, const float* __restrict__ W2,
                        const float* __restrict__ bias, void* __restrict__ C,
                        int M, int N, int outmode) {
    __shared__ float Asm[32][68];
    __shared__ float Wsm[32][64];
    int tid = threadIdx.x;
    int tx = tid & 15, ty = tid >> 4;
    int r0 = blockIdx.x * 64, c0 = blockIdx.y * 64;

    float acc[4][4];
#pragma unroll
    for (int i = 0; i < 4; i++)
#pragma unroll
        for (int j = 0; j < 4; j++) acc[i][j] = 0.f;

    int npass = (A2 != nullptr) ? 2 : 1;
    for (int p = 0; p < npass; ++p) {
        const float* Ap = p ? A2 : A;
        const float* Wp = p ? W2 : W;
        for (int kk = 0; kk < 128; kk += 32) {
            __syncthreads();
            {
                int k = tid & 31, r = tid >> 5;
#pragma unroll
                for (int pp = 0; pp < 8; ++pp) {
                    int row = r0 + r + pp * 8;
                    row = min(row, M - 1);
                    Asm[k][r + pp * 8] = Ap[(size_t)row * 128 + kk + k];
                }
            }
            {
                int c = tid & 63, kq = tid >> 6;
#pragma unroll
                for (int pp = 0; pp < 8; ++pp)
                    Wsm[kq + pp * 4][c] = Wp[(size_t)(kk + kq + pp * 4) * N + c0 + c];
            }
            __syncthreads();
#pragma unroll
            for (int k = 0; k < 32; ++k) {
                float4 a4 = *(const float4*)&Asm[k][ty * 4];
                float4 w4 = *(const float4*)&Wsm[k][tx * 4];
                float ar[4] = {a4.x, a4.y, a4.z, a4.w};
                float wc[4] = {w4.x, w4.y, w4.z, w4.w};
#pragma unroll
                for (int i = 0; i < 4; i++)
#pragma unroll
                    for (int j = 0; j < 4; j++)
                        acc[i][j] = fmaf(ar[i], wc[j], acc[i][j]);
            }
        }
    }
#pragma unroll
    for (int i = 0; i < 4; i++) {
        int row = r0 + ty * 4 + i;
        if (row < M) {
#pragma unroll
            for (int j = 0; j < 4; j++) {
                int col = c0 + tx * 4 + j;
                float v = acc[i][j] + (bias ? bias[col] : 0.f);
                if (outmode == 1) v = fmaxf(v, 0.f);
                if (outmode == 2)
                    ((__nv_bfloat16*)C)[(size_t)row * N + col] = __float2bfloat16(v);
                else
                    ((float*)C)[(size_t)row * N + col] = v;
            }
        }
    }
}

// ------- tensor-core LSTM: 4-warp groups, 3 groups/CTA, P prefetch -------
#define LGROUPS 3
#define HSTRIDE 136
#define SM_WF    0
#define SM_BIAS  131072
#define SM_HSTG  133120
#define SM_NID   (SM_HSTG + LGROUPS * 16 * HSTRIDE * 2)
#define SM_USM   (SM_NID + LGROUPS * 64)
#define SM_TOTAL (SM_USM + LGROUPS * 16 * MAXD * 4)

__global__ __launch_bounds__(32 * 4 * LGROUPS, 1)
void lstm_mma(const int* __restrict__ nbr) {
    extern __shared__ char smr[];
    uint2*  wf  = (uint2*)(smr + SM_WF);
    float4* bsm = (float4*)(smr + SM_BIAS);
    __nv_bfloat16* hstg = (__nv_bfloat16*)(smr + SM_HSTG);
    int* nidA = (int*)(smr + SM_NID);
    int* usmA = (int*)(smr + SM_USM);

    int tid = threadIdx.x, wid = tid >> 5, lane = tid & 31;
    for (int i = tid; i < 512 * 32; i += 32 * 4 * LGROUPS) wf[i] = g_Wfrag[i];
    if (tid < HID) bsm[tid] = g_biasF[tid];
    __syncthreads();

    int grp = wid >> 2, chunk = wid & 3;
    __nv_bfloat16* hs = hstg + grp * 16 * HSTRIDE;
    int* mynid = nidA + grp * 16;
    int* usm   = usmA + grp * 16 * MAXD;
    int r0 = lane >> 2, q = lane & 3;
    int barid = grp + 1;
    int nb = g_nbatch;
    const unsigned* PB = (const unsigned*)g_Pb;   // row stride 256 words

    for (int b = blockIdx.x * LGROUPS + grp; b < nb; b += gridDim.x * LGROUPS) {
        asm volatile("bar.sync %0, %1;" :: "r"(barid), "r"(128) : "memory"); // prev batch fully done
        int start = g_batch_start[b];
        int info  = g_batch_info[b];
        int dmax = info >> 8, cnt = info & 255;
        if (chunk == 0 && lane < 16) {
            int nid = g_order[start + min(lane, cnt - 1)];
            mynid[lane] = nid;
            const int4* src = (const int4*)(nbr + nid * MAXD);
            int4* dst = (int4*)(usm + lane * MAXD);
            dst[0] = src[0]; dst[1] = src[1]; dst[2] = src[2]; dst[3] = src[3];
        }
        asm volatile("bar.sync %0, %1;" :: "r"(barid), "r"(128) : "memory"); // publish ids

        float cst[16];
#pragma unroll
        for (int i = 0; i < 16; ++i) cst[i] = 0.f;

        // prefetch P for t=0
        unsigned pnl[16], pnh[16];
        {
            int u_lo = usm[r0 * MAXD], u_hi = usm[(r0 + 8) * MAXD];
            const unsigned* L = PB + (size_t)u_lo * 256;
            const unsigned* H = PB + (size_t)u_hi * 256;
#pragma unroll
            for (int nt = 0; nt < 16; ++nt) {
                int w = chunk * 64 + nt * 4 + q;
                pnl[nt] = L[w]; pnh[nt] = H[w];
            }
        }

        for (int t = 0; t < dmax; ++t) {
            unsigned pcl[16], pch[16];
#pragma unroll
            for (int nt = 0; nt < 16; ++nt) { pcl[nt] = pnl[nt]; pch[nt] = pnh[nt]; }

            // prev step's hs writes visible
            asm volatile("bar.sync %0, %1;" :: "r"(barid), "r"(128) : "memory");
            unsigned a[8][4];
            if (t > 0) {
#pragma unroll
                for (int kt = 0; kt < 8; ++kt) {
                    const __nv_bfloat16* hb = hs + kt * 16 + q * 2;
                    a[kt][0] = *(const unsigned*)(hb + r0 * HSTRIDE);
                    a[kt][1] = *(const unsigned*)(hb + (r0 + 8) * HSTRIDE);
                    a[kt][2] = *(const unsigned*)(hb + r0 * HSTRIDE + 8);
                    a[kt][3] = *(const unsigned*)(hb + (r0 + 8) * HSTRIDE + 8);
                }
            }
            // prefetch P for t+1 (hidden behind MMA + epilogue)
            if (t + 1 < dmax) {
                int u_lo = usm[r0 * MAXD + t + 1], u_hi = usm[(r0 + 8) * MAXD + t + 1];
                const unsigned* L = PB + (size_t)u_lo * 256;
                const unsigned* H = PB + (size_t)u_hi * 256;
#pragma unroll
                for (int nt = 0; nt < 16; ++nt) {
                    int w = chunk * 64 + nt * 4 + q;
                    pnl[nt] = L[w]; pnh[nt] = H[w];
                }
            }
            // hs reads done before epilogue overwrites
            asm volatile("bar.sync %0, %1;" :: "r"(barid), "r"(128) : "memory");

            bool last = (t == dmax - 1);
#pragma unroll
            for (int p = 0; p < 8; ++p) {
                float aE[4] = {0.f, 0.f, 0.f, 0.f};
                float aO[4] = {0.f, 0.f, 0.f, 0.f};
                if (t > 0) {
#pragma unroll
                    for (int kt = 0; kt < 8; ++kt) {
                        uint2 bE = wf[((kt << 6) + (chunk << 4) + 2 * p) * 32 + lane];
                        uint2 bO = wf[((kt << 6) + (chunk << 4) + 2 * p + 1) * 32 + lane];
                        mma16816(aE, a[kt], bE.x, bE.y);
                        mma16816(aO, a[kt], bO.x, bO.y);
                    }
                }
                int J = chunk * 32 + p * 4 + q;
                float4 bs = bsm[J];
                {   // node row r0
                    float gi = aE[0] + blo(pcl[2 * p])     + bs.x;
                    float gf = aE[1] + bhi(pcl[2 * p])     + bs.y;
                    float gg = aO[0] + blo(pcl[2 * p + 1]) + bs.z;
                    float go = aO[1] + bhi(pcl[2 * p + 1]) + bs.w;
                    float cn = sigt(gf) * cst[2 * p] + sigt(gi) * tanhap(gg);
                    cst[2 * p] = cn;
                    float h = sigt(go) * tanhap(cn);
                    if (!last) hs[r0 * HSTRIDE + J] = __float2bfloat16(h);
                    else if (r0 < cnt) g_hT[(size_t)mynid[r0] * HID + J] = h;
                }
                {   // node row r0+8
                    float gi = aE[2] + blo(pch[2 * p])     + bs.x;
                    float gf = aE[3] + bhi(pch[2 * p])     + bs.y;
                    float gg = aO[2] + blo(pch[2 * p + 1]) + bs.z;
                    float go = aO[3] + bhi(pch[2 * p + 1]) + bs.w;
                    float cn = sigt(gf) * cst[2 * p + 1] + sigt(gi) * tanhap(gg);
                    cst[2 * p + 1] = cn;
                    float h = sigt(go) * tanhap(cn);
                    if (!last) hs[(r0 + 8) * HSTRIDE + J] = __float2bfloat16(h);
                    else if (r0 + 8 < cnt) g_hT[(size_t)mynid[r0 + 8] * HID + J] = h;
                }
            }
        }
    }
}

// ---------------- GraphConv aggregate ----------------
__global__ void agg_kernel(const int* __restrict__ nbr, const int* __restrict__ deg) {
    int wid  = (blockIdx.x * blockDim.x + threadIdx.x) >> 5;
    int lane = threadIdx.x & 31;
    if (wid >= NNODES) return;
    int d = deg[wid];
    const int* nb = nbr + wid * MAXD;
    float4 acc = {0.f, 0.f, 0.f, 0.f};
    for (int t = 0; t < d; ++t) {
        int u = nb[t];
        float nu = rsqrtf((float)max(deg[u], 1));
        float4 v = *(const float4*)(g_h1 + (size_t)u * 128 + lane * 4);
        acc.x = fmaf(v.x, nu, acc.x); acc.y = fmaf(v.y, nu, acc.y);
        acc.z = fmaf(v.z, nu, acc.z); acc.w = fmaf(v.w, nu, acc.w);
    }
    float nn = rsqrtf((float)max(d, 1));
    float4 o = {acc.x * nn, acc.y * nn, acc.z * nn, acc.w * nn};
    *(float4*)(g_agg + (size_t)wid * 128 + lane * 4) = o;
}

// ---------------- GRU ----------------
__global__ void gru_kernel(const float* __restrict__ bih, const float* __restrict__ bhh) {
    extern __shared__ char sm[];
    float4* Wt   = (float4*)sm;
    float*  hrow = (float*)(sm + 65536);
    int tid = threadIdx.x;
    for (int i = tid; i < HID * GRUH; i += blockDim.x) Wt[i] = g_Wt3[i];
    __syncthreads();

    int w = tid >> 5, lane = tid & 31;
    float br = bih[lane], bz = bih[32 + lane], bn = bih[64 + lane];
    float cr = bhh[lane], cz = bhh[32 + lane], cnb = bhh[64 + lane];
    float* hr = hrow + w * 128;
    int nwarp = gridDim.x * 8;
    for (int node = blockIdx.x * 8 + w; node < NNODES; node += nwarp) {
        const float* h2 = g_h2 + (size_t)node * 128;
        *(float4*)(hr + lane * 4) = *(const float4*)(h2 + lane * 4);
        __syncwarp();
        float ar = 0.f, az = 0.f, an = 0.f;
#pragma unroll 8
        for (int k = 0; k < 128; ++k) {
            float hk = hr[k];
            float4 wv = Wt[k * 32 + lane];
            ar = fmaf(hk, wv.x, ar);
            az = fmaf(hk, wv.y, az);
            an = fmaf(hk, wv.z, an);
        }
        __syncwarp();
        float r   = sigf(ar + br + cr);
        float z   = sigf(az + bz + cz);
        float nst = tanh_(an + bn + r * cnb);
        g_o32[(size_t)node * 32 + lane] = (1.f - z) * nst;
    }
}

// ---------------- mean pool + classifier ----------------
__global__ void pool_kernel(const int* __restrict__ gid,
                            const float* __restrict__ Wc,
                            const float* __restrict__ bc,
                            float* __restrict__ out) {
    __shared__ float s[8][32];
    __shared__ int   scnt[8];
    __shared__ float hg[32];
    int g = blockIdx.x;
    int tid = threadIdx.x, lane = tid & 31, slot = tid >> 5;
    float acc = 0.f;
    int cnt = 0;
    for (int i = slot; i < NNODES; i += 8) {
        if (gid[i] == g) {
            acc += g_o32[(size_t)i * 32 + lane];
            cnt++;
        }
    }
    s[slot][lane] = acc;
    if (lane == 0) scnt[slot] = cnt;
    __syncthreads();
    if (tid < 32) {
        float sum = 0.f; int tot = 0;
#pragma unroll
        for (int j = 0; j < 8; ++j) { sum += s[j][tid]; tot += scnt[j]; }
        hg[tid] = sum / (float)tot;
    }
    __syncthreads();
    if (tid < NCLS) {
        float o = bc[tid];
#pragma unroll
        for (int k = 0; k < 32; ++k) o = fmaf(hg[k], Wc[k * NCLS + tid], o);
        out[g * NCLS + tid] = o;
    }
}

// ---------------- launch ----------------
extern "C" void kernel_launch(void* const* d_in, const int* in_sizes, int n_in,
                              void* d_out, int out_size) {
    const float* feature = (const float*)d_in[0];
    const int*   nbr     = (const int*)  d_in[1];
    const int*   deg     = (const int*)  d_in[2];
    const int*   gid     = (const int*)  d_in[3];
    const float* lWih    = (const float*)d_in[4];
    const float* lWhh    = (const float*)d_in[5];
    const float* lbih    = (const float*)d_in[6];
    const float* lbhh    = (const float*)d_in[7];
    const float* Wself   = (const float*)d_in[8];
    const float* Wneigh  = (const float*)d_in[9];
    const float* bsage   = (const float*)d_in[10];
    const float* Wgc     = (const float*)d_in[11];
    const float* bgc     = (const float*)d_in[12];
    const float* Wgru    = (const float*)d_in[13];
    const float* bihg    = (const float*)d_in[14];
    const float* bhhg    = (const float*)d_in[15];
    const float* Wcls    = (const float*)d_in[16];
    const float* bcls    = (const float*)d_in[17];
    float* out = (float*)d_out;

    cudaFuncSetAttribute(lstm_mma, cudaFuncAttributeMaxDynamicSharedMemorySize, SM_TOTAL);
    cudaFuncSetAttribute(gru_kernel, cudaFuncAttributeMaxDynamicSharedMemorySize, 69632 + 256);

    void *pPb, *pWihTp, *phT, *ph1, *pagg, *ph2;
    cudaGetSymbolAddress(&pPb,    g_Pb);
    cudaGetSymbolAddress(&pWihTp, g_WihTp);
    cudaGetSymbolAddress(&phT,    g_hT);
    cudaGetSymbolAddress(&ph1,    g_h1);
    cudaGetSymbolAddress(&pagg,   g_agg);
    cudaGetSymbolAddress(&ph2,    g_h2);

    prep_kernel<<<256, 256>>>(lWih, lWhh, lbih, lbhh, Wgru);

    k_zero<<<1, 32>>>();
    k_hist<<<98, 512>>>(deg);
    k_batches<<<1, 32>>>();
    k_scatter<<<(NNODES + 511) / 512, 512>>>(deg);

    // P = feature @ WihT_perm -> bf16 permuted [N,512]
    {
        dim3 grid((NNODES + 63) / 64, 512 / 64);
        gemm128<<<grid, 256>>>(feature, (const float*)pWihTp, nullptr, nullptr,
                               nullptr, pPb, NNODES, 512, 2);
    }
    // tensor-core LSTM
    lstm_mma<<<152, 32 * 4 * LGROUPS, SM_TOTAL>>>(nbr);
    // h1 = relu(feature@W_self + hT@W_neigh + b_sage)
    {
        dim3 grid((NNODES + 63) / 64, 128 / 64);
        gemm128<<<grid, 256>>>(feature, Wself, (const float*)phT, Wneigh,
                               bsage, ph1, NNODES, 128, 1);
    }
    agg_kernel<<<(NNODES * 32 + 255) / 256, 256>>>(nbr, deg);
    {
        dim3 grid((NNODES + 63) / 64, 128 / 64);
        gemm128<<<grid, 256>>>((const float*)pagg, Wgc, nullptr, nullptr,
                               bgc, ph2, NNODES, 128, 1);
    }
    gru_kernel<<<304, 256, 69632 + 256>>>(bihg, bhhg);
    pool_kernel<<<NGRAPH, 256>>>(gid, Wcls, bcls, out);
}